// round 8
// baseline (speedup 1.0000x reference)
#include <cuda_runtime.h>
#include <cuda_fp16.h>
#include <float.h>
#include <math.h>
#include <cstdint>

#define BB 8
#define NN 2048
#define DD 512

// ---------------------------------------------------------------------------
// Scratch (__device__ globals only — allocation-free contract)
// ---------------------------------------------------------------------------
__device__ float g_xx[BB * NN];
__device__ float g_dist[(size_t)BB * NN * NN];          // 134 MB
__device__ __half g_sp[2][(size_t)BB * NN * DD];        // h / l fp16 splits, 32 MB

__device__ __forceinline__ uint32_t smem_u32(const void* p) {
    uint32_t a;
    asm("{ .reg .u64 t; cvta.to.shared.u64 t, %1; cvt.u32.u64 %0, t; }" : "=r"(a) : "l"(p));
    return a;
}

#define LDSM4(r0, r1, r2, r3, addr) \
    asm volatile("ldmatrix.sync.aligned.m8n8.x4.shared.b16 {%0,%1,%2,%3}, [%4];" \
                 : "=r"(r0), "=r"(r1), "=r"(r2), "=r"(r3) : "r"(addr))

#define MMA16816(c, a, b0, b1) \
    asm volatile("mma.sync.aligned.m16n8k16.row.col.f32.f16.f16.f32 " \
                 "{%0,%1,%2,%3}, {%4,%5,%6,%7}, {%8,%9}, {%0,%1,%2,%3};" \
                 : "+f"((c)[0]), "+f"((c)[1]), "+f"((c)[2]), "+f"((c)[3]) \
                 : "r"((a)[0]), "r"((a)[1]), "r"((a)[2]), "r"((a)[3]), "r"(b0), "r"(b1))

#define CP_ASYNC16(dst, src) \
    asm volatile("cp.async.cg.shared.global [%0], [%1], 16;" :: "r"(dst), "l"(src))
#define CP_COMMIT() asm volatile("cp.async.commit_group;" ::: "memory")

// ---------------------------------------------------------------------------
// Kernel 0: fp16 2-word split of put  (x = h + l exactly to 2^-22)
// ---------------------------------------------------------------------------
__global__ __launch_bounds__(256) void split_kernel(const float* __restrict__ put) {
    size_t i4 = ((size_t)blockIdx.x * 256 + threadIdx.x) * 4;
    float4 v = *(const float4*)(put + i4);
    float x[4] = {v.x, v.y, v.z, v.w};
    __half h[4], l[4];
#pragma unroll
    for (int q = 0; q < 4; q++) {
        h[q] = __float2half(x[q]);
        l[q] = __float2half(x[q] - __half2float(h[q]));
    }
    *(uint2*)(&g_sp[0][i4]) = *(uint2*)h;
    *(uint2*)(&g_sp[1][i4]) = *(uint2*)l;
}

// ---------------------------------------------------------------------------
// Kernel 1: row squared norms (fp32 exact)
// ---------------------------------------------------------------------------
__global__ __launch_bounds__(256) void xx_kernel(const float* __restrict__ put) {
    int row  = blockIdx.x * 8 + (threadIdx.x >> 5);
    int lane = threadIdx.x & 31;
    const float* p = put + (size_t)row * DD;
    float s = 0.f;
#pragma unroll
    for (int f = 0; f < 4; f++) {
        float4 v = *(const float4*)(p + f * 128 + lane * 4);
        s = fmaf(v.x, v.x, s); s = fmaf(v.y, v.y, s);
        s = fmaf(v.z, v.z, s); s = fmaf(v.w, v.w, s);
    }
#pragma unroll
    for (int off = 16; off; off >>= 1) s += __shfl_xor_sync(0xffffffffu, s, off);
    if (lane == 0) g_xx[row] = s;
}

// ---------------------------------------------------------------------------
// Kernel 2: distance tiles — single launch (16,16,8). UNCHANGED (at roofline).
// ---------------------------------------------------------------------------
#define PITCH_H 40
#define TILE_B  (128 * PITCH_H * 2)
#define BUF_B   (4 * TILE_B)
#define XX_OFF  (2 * BUF_B)
#define SM_TOTAL (XX_OFF + 1024)
#define T_PITCH 136

__global__ __launch_bounds__(256, 1) void dist_mma_kernel() {
    int bx = blockIdx.x, by = blockIdx.y, b = blockIdx.z;
    if (by > bx) return;
    bool diag = (bx == by);

    extern __shared__ char smem[];
    uint32_t sbase = smem_u32(smem);
    int tid  = threadIdx.x;
    int lane = tid & 31;
    int wid  = tid >> 5;

    int j0 = by * 128, i0 = bx * 128, bofs = b * NN;

    float* xxA = (float*)(smem + XX_OFF);
    float* xxB = (float*)(smem + XX_OFF + 512);
    if (tid < 128) {
        xxA[tid] = g_xx[bofs + j0 + tid];
        xxB[tid] = g_xx[bofs + i0 + tid];
    }

    int fr   = (tid >> 2);
    int fck  = tid & 3;
    auto fill = [&](int buf, int kt) {
#pragma unroll
        for (int q = 0; q < 8; q++) {
            int rr   = fr + 64 * (q & 1);
            int tile = q >> 1;
            int word = tile & 1;
            int grow = (tile < 2 ? j0 : i0) + rr;
            const __half* src = &g_sp[word][(size_t)(bofs + grow) * DD + kt * 32 + fck * 8];
            uint32_t dst = sbase + buf * BUF_B + tile * TILE_B + rr * (PITCH_H * 2) + fck * 16;
            CP_ASYNC16(dst, src);
        }
    };

    int wm = (wid >> 2) * 64;
    int wn = (wid & 3) * 32;

    float acc[4][4][4];
#pragma unroll
    for (int im = 0; im < 4; im++)
#pragma unroll
        for (int in = 0; in < 4; in++)
#pragma unroll
            for (int q = 0; q < 4; q++) acc[im][in][q] = 0.f;

    fill(0, 0);
    CP_COMMIT();

    int arow = lane & 15;
    int acol = (lane >> 4) * 8;
    int brow = (lane & 7) + ((lane >> 4) << 3);
    int bcol = ((lane >> 3) & 1) * 8;

    for (int kt = 0; kt < 16; kt++) {
        if (kt < 15) { fill((kt + 1) & 1, kt + 1); CP_COMMIT(); }
        if (kt < 15) asm volatile("cp.async.wait_group 1;" ::: "memory");
        else         asm volatile("cp.async.wait_group 0;" ::: "memory");
        __syncthreads();

        uint32_t base = sbase + (kt & 1) * BUF_B;
#pragma unroll
        for (int kc = 0; kc < 2; kc++) {
            int kofs = kc * 16;
            uint32_t ah[4][4], al[4][4];
#pragma unroll
            for (int im = 0; im < 4; im++) {
                uint32_t off = (uint32_t)((wm + im * 16 + arow) * (PITCH_H * 2) + (kofs + acol) * 2);
                LDSM4(ah[im][0], ah[im][1], ah[im][2], ah[im][3], base + 0 * TILE_B + off);
                LDSM4(al[im][0], al[im][1], al[im][2], al[im][3], base + 1 * TILE_B + off);
            }
            uint32_t bh[8], bl[8];
#pragma unroll
            for (int bp = 0; bp < 2; bp++) {
                uint32_t off = (uint32_t)((wn + bp * 16 + brow) * (PITCH_H * 2) + (kofs + bcol) * 2);
                LDSM4(bh[bp*4+0], bh[bp*4+1], bh[bp*4+2], bh[bp*4+3], base + 2 * TILE_B + off);
                LDSM4(bl[bp*4+0], bl[bp*4+1], bl[bp*4+2], bl[bp*4+3], base + 3 * TILE_B + off);
            }
#pragma unroll
            for (int im = 0; im < 4; im++)
#pragma unroll
                for (int in = 0; in < 4; in++) {
                    MMA16816(acc[im][in], ah[im], bh[in*2], bh[in*2+1]);
                    MMA16816(acc[im][in], ah[im], bl[in*2], bl[in*2+1]);
                    MMA16816(acc[im][in], al[im], bh[in*2], bh[in*2+1]);
                }
        }
        __syncthreads();
    }

    float* smemT = (float*)smem;

#pragma unroll
    for (int im = 0; im < 4; im++) {
#pragma unroll
        for (int h2 = 0; h2 < 2; h2++) {
            int row = wm + im * 16 + (lane >> 2) + h2 * 8;
            float xj = xxA[row];
#pragma unroll
            for (int in = 0; in < 4; in++) {
                int n = wn + in * 8 + (lane & 3) * 2;
                float g0 = acc[im][in][h2 * 2 + 0];
                float g1 = acc[im][in][h2 * 2 + 1];
                float v0 = sqrtf(fmaxf((xj + xxB[n])     - 2.0f * g0, 0.0f));
                float v1 = sqrtf(fmaxf((xj + xxB[n + 1]) - 2.0f * g1, 0.0f));
                *(float2*)&g_dist[((size_t)(bofs + j0 + row)) * NN + i0 + n] = make_float2(v0, v1);
                if (!diag) {
                    smemT[(n)     * T_PITCH + row] = v0;
                    smemT[(n + 1) * T_PITCH + row] = v1;
                }
            }
        }
    }

    if (!diag) {
        __syncthreads();
#pragma unroll
        for (int q = 0; q < 16; q++) {
            int fid = tid + 256 * q;
            int nrow = fid >> 5, f4 = fid & 31;
            float4 val = *(float4*)&smemT[nrow * T_PITCH + f4 * 4];
            *(float4*)&g_dist[((size_t)(bofs + i0 + nrow)) * NN + j0 + f4 * 4] = val;
        }
    }
}

// ---------------------------------------------------------------------------
// Kernel 3: warp-autonomous top-16 radix select. 1 warp = 1 row, NO block
// barriers. 4 warps/block. Exact stable (val, idx) semantics.
// ---------------------------------------------------------------------------
#define WCAP 256
// smem word offsets (per block, 4 warps):
//  rows 0..8191 | hist 8192..9215 | cv 9216..10239 | ci 10240..11263
//  sure 11264..11327 | widx 11328..11391 | cnt 11392..11399
#define TKW_SMEM_BYTES (11400 * 4)

__device__ __forceinline__ void cmin3(uint32_t& v, uint32_t& i, uint32_t& j,
                                      uint32_t v2, uint32_t i2, uint32_t j2) {
    if (v2 < v || (v2 == v && i2 < i)) { v = v2; i = i2; j = j2; }
}
__device__ __forceinline__ void cmin2(uint32_t& v, uint32_t& i, uint32_t v2, uint32_t i2) {
    if (v2 < v || (v2 == v && i2 < i)) { v = v2; i = i2; }
}

__global__ __launch_bounds__(128) void topk_warp_kernel(float* __restrict__ out) {
    extern __shared__ uint32_t sh[];
    const uint32_t FULL = 0xffffffffu;
    int tid  = threadIdx.x;
    int lane = tid & 31;
    int wid  = tid >> 5;

    size_t row = (size_t)blockIdx.x * 4 + wid;
    uint32_t* rowb = sh + wid * 2048;
    uint32_t* hist = sh + 8192  + wid * 256;
    uint32_t* cv   = sh + 9216  + wid * WCAP;
    uint32_t* ci   = sh + 10240 + wid * WCAP;
    uint32_t* sure = sh + 11264 + wid * 16;
    uint32_t* widx = sh + 11328 + wid * 16;
    uint32_t* cnt  = sh + 11392 + wid * 2;

    // ---- stage row into warp-private smem; fuse output zeroing ----
    const uint4* src = (const uint4*)(g_dist + row * NN);
    float* orow = out + row * NN;
    float4 z = make_float4(0.f, 0.f, 0.f, 0.f);
#pragma unroll
    for (int c = 0; c < 16; c++) {
        ((uint4*)rowb)[c * 32 + lane]  = src[c * 32 + lane];
        ((float4*)orow)[c * 32 + lane] = z;
    }
#pragma unroll
    for (int i = 0; i < 8; i++) hist[i * 32 + lane] = 0;
    if (lane == 0) { cnt[0] = 0; cnt[1] = 0; }
    __syncwarp();

    // ---- level-0 hist: byte v>>24, warp-aggregated atomics ----
#pragma unroll
    for (int c = 0; c < 16; c++) {
        uint4 v4 = ((uint4*)rowb)[c * 32 + lane];
        uint32_t vv[4] = {v4.x, v4.y, v4.z, v4.w};
#pragma unroll
        for (int j = 0; j < 4; j++) {
            uint32_t bin = vv[j] >> 24;
            uint32_t mk = __match_any_sync(FULL, bin);
            if (lane == __ffs(mk) - 1) atomicAdd(&hist[bin], __popc(mk));
        }
    }
    __syncwarp();

    // ---- warp scan: find level-0 bin of the 16th smallest ----
    uint32_t b0, c0;
    {
        uint32_t loc[8], s = 0;
#pragma unroll
        for (int i = 0; i < 8; i++) { loc[i] = hist[lane * 8 + i]; s += loc[i]; }
        uint32_t incl = s;
#pragma unroll
        for (int o = 1; o < 32; o <<= 1) {
            uint32_t t = __shfl_up_sync(FULL, incl, o);
            if (lane >= o) incl += t;
        }
        uint32_t run = incl - s;
        uint32_t fb = 0xffffffffu, fc = 0;
#pragma unroll
        for (int i = 0; i < 8; i++) {
            if (run < 16u && 16u <= run + loc[i]) { fb = lane * 8 + i; fc = run; }
            run += loc[i];
        }
        uint32_t bal = __ballot_sync(FULL, fb != 0xffffffffu);
        int sl = __ffs(bal) - 1;
        b0 = __shfl_sync(FULL, fb, sl);
        c0 = __shfl_sync(FULL, fc, sl);
    }
    __syncwarp();
#pragma unroll
    for (int i = 0; i < 8; i++) hist[i * 32 + lane] = 0;
    __syncwarp();

    // ---- level-1 hist: bits [23:16] where top byte == b0 ----
#pragma unroll
    for (int c = 0; c < 16; c++) {
        uint4 v4 = ((uint4*)rowb)[c * 32 + lane];
        uint32_t vv[4] = {v4.x, v4.y, v4.z, v4.w};
#pragma unroll
        for (int j = 0; j < 4; j++) {
            bool act = ((vv[j] >> 24) == b0);
            uint32_t bin = act ? ((vv[j] >> 16) & 255u) : (256u + lane);
            uint32_t mk = __match_any_sync(FULL, bin);
            if (act && lane == __ffs(mk) - 1) atomicAdd(&hist[bin], __popc(mk));
        }
    }
    __syncwarp();

    // ---- warp scan: level-1 prefix P, count below (clt) ----
    uint32_t P, clt;
    {
        uint32_t k1 = 16u - c0;
        uint32_t loc[8], s = 0;
#pragma unroll
        for (int i = 0; i < 8; i++) { loc[i] = hist[lane * 8 + i]; s += loc[i]; }
        uint32_t incl = s;
#pragma unroll
        for (int o = 1; o < 32; o <<= 1) {
            uint32_t t = __shfl_up_sync(FULL, incl, o);
            if (lane >= o) incl += t;
        }
        uint32_t run = incl - s;
        uint32_t fP = 0xffffffffu, fc = 0;
#pragma unroll
        for (int i = 0; i < 8; i++) {
            if (run < k1 && k1 <= run + loc[i]) { fP = (b0 << 8) | (uint32_t)(lane * 8 + i); fc = c0 + run; }
            run += loc[i];
        }
        uint32_t bal = __ballot_sync(FULL, fP != 0xffffffffu);
        int sl = __ffs(bal) - 1;
        P   = __shfl_sync(FULL, fP, sl);
        clt = __shfl_sync(FULL, fc, sl);
    }

    // ---- gather: sure (prefix < P) + candidates (prefix == P) ----
#pragma unroll
    for (int c = 0; c < 16; c++) {
        uint4 v4 = ((uint4*)rowb)[c * 32 + lane];
        uint32_t vv[4] = {v4.x, v4.y, v4.z, v4.w};
#pragma unroll
        for (int j = 0; j < 4; j++) {
            uint32_t hi = vv[j] >> 16;
            uint32_t idx = (uint32_t)(c * 32 + lane) * 4 + j;
            if (hi < P) {
                uint32_t p = atomicAdd(&cnt[0], 1u);
                sure[p] = idx;
            } else if (hi == P) {
                uint32_t p = atomicAdd(&cnt[1], 1u);
                if (p < WCAP) { cv[p] = vv[j]; ci[p] = idx; }
            }
        }
    }
    __syncwarp();

    uint32_t m = 16u - clt;
    uint32_t n = cnt[1];

    if (n <= WCAP) {
        // fast path: stable-min rounds over candidate list
        for (uint32_t it = 0; it < m; it++) {
            uint32_t bv = FULL, bi = FULL, bj = FULL;
            for (uint32_t j = lane; j < n; j += 32)
                cmin3(bv, bi, bj, cv[j], ci[j], j);
#pragma unroll
            for (int o = 16; o; o >>= 1) {
                uint32_t ov = __shfl_down_sync(FULL, bv, o);
                uint32_t oi = __shfl_down_sync(FULL, bi, o);
                uint32_t oj = __shfl_down_sync(FULL, bj, o);
                cmin3(bv, bi, bj, ov, oi, oj);
            }
            if (lane == 0) {
                widx[it] = bi;
                cv[bj] = FULL; ci[bj] = FULL;
            }
            __syncwarp();
        }
    } else {
        // slow fallback (never expected): rounds scan the row directly
        for (uint32_t it = 0; it < m; it++) {
            uint32_t bv = FULL, bi = FULL;
#pragma unroll
            for (int c = 0; c < 16; c++) {
                uint4 v4 = ((uint4*)rowb)[c * 32 + lane];
                uint32_t vv[4] = {v4.x, v4.y, v4.z, v4.w};
#pragma unroll
                for (int j = 0; j < 4; j++) {
                    if ((vv[j] >> 16) == P)
                        cmin2(bv, bi, vv[j], (uint32_t)(c * 32 + lane) * 4 + j);
                }
            }
#pragma unroll
            for (int o = 16; o; o >>= 1) {
                uint32_t ov = __shfl_down_sync(FULL, bv, o);
                uint32_t oi = __shfl_down_sync(FULL, bi, o);
                cmin2(bv, bi, ov, oi);
            }
            bi = __shfl_sync(FULL, bi, 0);
            if (lane == 0) { widx[it] = bi; rowb[bi] = FULL; }
            __syncwarp();
        }
    }
    __syncwarp();

    // ---- scatter ones (zeros already written during staging) ----
    if (lane < clt) orow[sure[lane]] = 1.0f;
    if (lane < m)   orow[widx[lane]] = 1.0f;
}

// ---------------------------------------------------------------------------
extern "C" void kernel_launch(void* const* d_in, const int* in_sizes, int n_in,
                              void* d_out, int out_size) {
    const float* put = (const float*)d_in[0];
    float* out = (float*)d_out;

    cudaFuncSetAttribute(dist_mma_kernel, cudaFuncAttributeMaxDynamicSharedMemorySize, SM_TOTAL);
    cudaFuncSetAttribute(topk_warp_kernel, cudaFuncAttributeMaxDynamicSharedMemorySize, TKW_SMEM_BYTES);

    split_kernel<<<(BB * NN * DD) / (256 * 4), 256>>>(put);
    xx_kernel<<<(BB * NN) / 8, 256>>>(put);
    dist_mma_kernel<<<dim3(16, 16, BB), 256, SM_TOTAL>>>();
    topk_warp_kernel<<<(BB * NN) / 4, 128, TKW_SMEM_BYTES>>>(out);
}